// round 2
// baseline (speedup 1.0000x reference)
#include <cuda_runtime.h>
#include <math.h>

// Problem constants
#define B_   4
#define N_   2048
#define D_   1024
#define H_   16
#define HD_  64
#define E3_  192          // 3 * head_dim, chunk order (k, q, v)
#define MROWS (B_ * N_)   // 8192

#define NEG_INF (-1e30f)

// Scratch (allocation-free rule: __device__ globals)
__device__ float g_kqv[(size_t)B_ * H_ * N_ * E3_];  // [b][h][n][e]  ~100 MB
__device__ float g_sa [(size_t)B_ * N_ * D_];        // [b][n][h*hd+d] ~33 MB

// ---------------------------------------------------------------------------
// QKV projection: per head h, C[8192 x 192] = X[8192 x 1024] @ W_h[1024 x 192] + b_h
// Tile 64x64x16, 256 threads, 4x4 micro-tiles.
// ---------------------------------------------------------------------------
__global__ __launch_bounds__(256) void qkv_gemm_kernel(
    const float* __restrict__ X, const float* __restrict__ W,
    const float* __restrict__ bias)
{
    __shared__ float As[16][64];   // A transposed: As[k][m]
    __shared__ float Bs[16][64];   // Bs[k][n]

    const int h  = blockIdx.z;
    const int m0 = blockIdx.x * 64;
    const int n0 = blockIdx.y * 64;
    const float* Wh = W + (size_t)h * (D_ * E3_);

    const int tid  = threadIdx.x;
    const int ty   = tid >> 4, tx = tid & 15;
    const int arow = tid >> 2;            // 0..63
    const int akc  = (tid & 3) << 2;      // 0,4,8,12
    const int bkr  = tid >> 4;            // 0..15
    const int bcol = (tid & 15) << 2;     // 0..60

    float acc[4][4] = {};

    for (int k0 = 0; k0 < D_; k0 += 16) {
        float4 av = *(const float4*)(X + (size_t)(m0 + arow) * D_ + k0 + akc);
        As[akc + 0][arow] = av.x;
        As[akc + 1][arow] = av.y;
        As[akc + 2][arow] = av.z;
        As[akc + 3][arow] = av.w;
        *(float4*)(&Bs[bkr][bcol]) =
            *(const float4*)(Wh + (size_t)(k0 + bkr) * E3_ + n0 + bcol);
        __syncthreads();
#pragma unroll
        for (int k = 0; k < 16; ++k) {
            float4 a4 = *(const float4*)&As[k][ty << 2];
            float4 b4 = *(const float4*)&Bs[k][tx << 2];
            float a[4] = {a4.x, a4.y, a4.z, a4.w};
            float b[4] = {b4.x, b4.y, b4.z, b4.w};
#pragma unroll
            for (int i = 0; i < 4; ++i)
#pragma unroll
                for (int j = 0; j < 4; ++j)
                    acc[i][j] = fmaf(a[i], b[j], acc[i][j]);
        }
        __syncthreads();
    }

#pragma unroll
    for (int i = 0; i < 4; ++i) {
        int m = m0 + (ty << 2) + i;
        int b = m / N_, n = m - b * N_;
        int e = n0 + (tx << 2);
        float4 o;
        o.x = acc[i][0] + bias[h * E3_ + e + 0];
        o.y = acc[i][1] + bias[h * E3_ + e + 1];
        o.z = acc[i][2] + bias[h * E3_ + e + 2];
        o.w = acc[i][3] + bias[h * E3_ + e + 3];
        *(float4*)(g_kqv + (((size_t)b * H_ + h) * N_ + n) * E3_ + e) = o;
    }
}

// ---------------------------------------------------------------------------
// Causal flash attention: one block = 64 queries of one (b,h). Online softmax.
// Skips fully-masked key tiles (kt > qi): ~2x work saving.
// Smem: Qs (Q^T) + KP (K^T, reused for P) + Vs = exactly 48 KB.
// ---------------------------------------------------------------------------
__global__ __launch_bounds__(256) void attn_kernel()
{
    __shared__ float Qs[64][64];  // [d][r], pre-scaled by 1/sqrt(hd)
    __shared__ float KP[64][64];  // phase 1: K^T [d][c]; phase 2: P [r][c]
    __shared__ float Vs[64][64];  // [c][d]

    const int qi  = blockIdx.x;
    const int h   = blockIdx.y;
    const int b   = blockIdx.z;
    const int tid = threadIdx.x;
    const int ty  = tid >> 4, tx = tid & 15;
    const int lr  = tid >> 2;          // 0..63 (row being loaded)
    const int ld0 = (tid & 3) << 4;    // 0,16,32,48 (dim offset)

    const size_t base  = ((size_t)b * H_ + h) * N_ * E3_;
    const int    qbase = qi * 64;

    // Load Q tile transposed, folding in 1/sqrt(64) = 0.125
    {
        const float* qp = g_kqv + base + (size_t)(qbase + lr) * E3_ + HD_; // q chunk
#pragma unroll
        for (int u = 0; u < 4; ++u) {
            int d = ld0 + (u << 2);
            float4 v = *(const float4*)(qp + d);
            Qs[d + 0][lr] = v.x * 0.125f;
            Qs[d + 1][lr] = v.y * 0.125f;
            Qs[d + 2][lr] = v.z * 0.125f;
            Qs[d + 3][lr] = v.w * 0.125f;
        }
    }

    float acc[4][4] = {};
    float mrow[4] = {NEG_INF, NEG_INF, NEG_INF, NEG_INF};
    float lrow[4] = {};

    for (int kt = 0; kt <= qi; ++kt) {
        __syncthreads();  // previous iteration done reading KP/Vs; Q store visible
        // Load K^T and V for this key tile
        {
            const int kbase = kt * 64;
            const float* kp = g_kqv + base + (size_t)(kbase + lr) * E3_;      // k chunk
            const float* vp = kp + 2 * HD_;                                   // v chunk
#pragma unroll
            for (int u = 0; u < 4; ++u) {
                int d = ld0 + (u << 2);
                float4 kv = *(const float4*)(kp + d);
                KP[d + 0][lr] = kv.x;
                KP[d + 1][lr] = kv.y;
                KP[d + 2][lr] = kv.z;
                KP[d + 3][lr] = kv.w;
                *(float4*)&Vs[lr][d] = *(const float4*)(vp + d);
            }
        }
        __syncthreads();

        // S = (Q/8) K^T  : 4x4 micro-tile per thread
        float s[4][4] = {};
#pragma unroll 8
        for (int k = 0; k < 64; ++k) {
            float4 a4 = *(const float4*)&Qs[k][ty << 2];
            float4 b4 = *(const float4*)&KP[k][tx << 2];
            float a[4]  = {a4.x, a4.y, a4.z, a4.w};
            float bb[4] = {b4.x, b4.y, b4.z, b4.w};
#pragma unroll
            for (int i = 0; i < 4; ++i)
#pragma unroll
                for (int j = 0; j < 4; ++j)
                    s[i][j] = fmaf(a[i], bb[j], s[i][j]);
        }

        // Causal mask (only the diagonal tile has masked entries)
        if (kt == qi) {
#pragma unroll
            for (int i = 0; i < 4; ++i) {
                int qg = (ty << 2) + i;
#pragma unroll
                for (int j = 0; j < 4; ++j)
                    if (((tx << 2) + j) > qg) s[i][j] = NEG_INF;
            }
        }

        // Online softmax update (row reductions via shfl over the 16 tx lanes)
        float p[4][4];
        float alpha[4];
#pragma unroll
        for (int i = 0; i < 4; ++i) {
            float mx = fmaxf(fmaxf(s[i][0], s[i][1]), fmaxf(s[i][2], s[i][3]));
#pragma unroll
            for (int o = 8; o > 0; o >>= 1)
                mx = fmaxf(mx, __shfl_xor_sync(0xffffffffu, mx, o));
            float mnew = fmaxf(mrow[i], mx);
            float a_ = __expf(mrow[i] - mnew);
            float sum = 0.f;
#pragma unroll
            for (int j = 0; j < 4; ++j) {
                float e = __expf(s[i][j] - mnew);
                p[i][j] = e;
                sum += e;
            }
#pragma unroll
            for (int o = 8; o > 0; o >>= 1)
                sum += __shfl_xor_sync(0xffffffffu, sum, o);
            lrow[i]  = lrow[i] * a_ + sum;
            mrow[i]  = mnew;
            alpha[i] = a_;
        }
#pragma unroll
        for (int i = 0; i < 4; ++i)
#pragma unroll
            for (int j = 0; j < 4; ++j) acc[i][j] *= alpha[i];

        __syncthreads();  // everyone done reading KP as K
        // Store P into KP buffer, layout [r][c]
#pragma unroll
        for (int i = 0; i < 4; ++i)
            *(float4*)&KP[(ty << 2) + i][tx << 2] =
                make_float4(p[i][0], p[i][1], p[i][2], p[i][3]);
        __syncthreads();

        // O += P @ V
        for (int c0 = 0; c0 < 64; c0 += 4) {
            float pr[4][4];
#pragma unroll
            for (int i = 0; i < 4; ++i) {
                float4 t = *(const float4*)&KP[(ty << 2) + i][c0];
                pr[i][0] = t.x; pr[i][1] = t.y; pr[i][2] = t.z; pr[i][3] = t.w;
            }
#pragma unroll
            for (int cc = 0; cc < 4; ++cc) {
                float4 v4 = *(const float4*)&Vs[c0 + cc][tx << 2];
                float vv[4] = {v4.x, v4.y, v4.z, v4.w};
#pragma unroll
                for (int i = 0; i < 4; ++i)
#pragma unroll
                    for (int j = 0; j < 4; ++j)
                        acc[i][j] = fmaf(pr[i][cc], vv[j], acc[i][j]);
            }
        }
    }

    // Normalize and write to g_sa with heads concatenated along feature dim
#pragma unroll
    for (int i = 0; i < 4; ++i) {
        float inv = 1.0f / lrow[i];
        int n = qbase + (ty << 2) + i;
        float4 o = make_float4(acc[i][0] * inv, acc[i][1] * inv,
                               acc[i][2] * inv, acc[i][3] * inv);
        *(float4*)(g_sa + ((size_t)b * N_ + n) * D_ + h * HD_ + (tx << 2)) = o;
    }
}

// ---------------------------------------------------------------------------
// Output projection: out[8192 x 1024] = g_sa @ W_proj + b_proj
// ---------------------------------------------------------------------------
__global__ __launch_bounds__(256) void proj_gemm_kernel(
    const float* __restrict__ W, const float* __restrict__ bias,
    float* __restrict__ out)
{
    __shared__ float As[16][64];
    __shared__ float Bs[16][64];

    const int m0 = blockIdx.x * 64;
    const int n0 = blockIdx.y * 64;

    const int tid  = threadIdx.x;
    const int ty   = tid >> 4, tx = tid & 15;
    const int arow = tid >> 2;
    const int akc  = (tid & 3) << 2;
    const int bkr  = tid >> 4;
    const int bcol = (tid & 15) << 2;

    float acc[4][4] = {};

    for (int k0 = 0; k0 < D_; k0 += 16) {
        float4 av = *(const float4*)(g_sa + (size_t)(m0 + arow) * D_ + k0 + akc);
        As[akc + 0][arow] = av.x;
        As[akc + 1][arow] = av.y;
        As[akc + 2][arow] = av.z;
        As[akc + 3][arow] = av.w;
        *(float4*)(&Bs[bkr][bcol]) =
            *(const float4*)(W + (size_t)(k0 + bkr) * D_ + n0 + bcol);
        __syncthreads();
#pragma unroll
        for (int k = 0; k < 16; ++k) {
            float4 a4 = *(const float4*)&As[k][ty << 2];
            float4 b4 = *(const float4*)&Bs[k][tx << 2];
            float a[4] = {a4.x, a4.y, a4.z, a4.w};
            float b[4] = {b4.x, b4.y, b4.z, b4.w};
#pragma unroll
            for (int i = 0; i < 4; ++i)
#pragma unroll
                for (int j = 0; j < 4; ++j)
                    acc[i][j] = fmaf(a[i], b[j], acc[i][j]);
        }
        __syncthreads();
    }

#pragma unroll
    for (int i = 0; i < 4; ++i) {
        int m = m0 + (ty << 2) + i;
        int e = n0 + (tx << 2);
        float4 o;
        o.x = acc[i][0] + bias[e + 0];
        o.y = acc[i][1] + bias[e + 1];
        o.z = acc[i][2] + bias[e + 2];
        o.w = acc[i][3] + bias[e + 3];
        *(float4*)(out + (size_t)m * D_ + e) = o;
    }
}

// ---------------------------------------------------------------------------
extern "C" void kernel_launch(void* const* d_in, const int* in_sizes, int n_in,
                              void* d_out, int out_size)
{
    const float* x      = (const float*)d_in[0];
    const float* W_kqv  = (const float*)d_in[1];
    const float* b_kqv  = (const float*)d_in[2];
    const float* W_proj = (const float*)d_in[3];
    const float* b_proj = (const float*)d_in[4];
    float* out = (float*)d_out;

    qkv_gemm_kernel<<<dim3(MROWS / 64, E3_ / 64, H_), 256>>>(x, W_kqv, b_kqv);
    attn_kernel<<<dim3(N_ / 64, H_, B_), 256>>>();
    proj_gemm_kernel<<<dim3(MROWS / 64, D_ / 64), 256>>>(W_proj, b_proj, out);
}